// round 1
// baseline (speedup 1.0000x reference)
#include <cuda_runtime.h>
#include <cuda_bf16.h>
#include <math.h>

// Problem dims
#define BB   16
#define CC   192
#define HW   2304          // 48*48
#define NTOT (BB*HW)       // 36864

// ------------------------------------------------------------------
// Scratch (device globals -- allocation-free rule)
// ------------------------------------------------------------------
__device__ float g_xn[(size_t)NTOT * CC];      // xn, later reused as attn@V output
__device__ float g_q [(size_t)NTOT * CC];
__device__ float g_k [(size_t)NTOT * CC];
__device__ float g_v [(size_t)NTOT * CC];
__device__ float g_s [(size_t)BB * HW * HW];   // 340 MB scores

// ------------------------------------------------------------------
// K1: LayerNorm over C with [B,C,HW] -> [B,N,C] transpose
// block: 256 threads, 32 spatial positions
// ------------------------------------------------------------------
__global__ __launch_bounds__(256) void ln_transpose_kernel(
    const float* __restrict__ x,
    const float* __restrict__ ln_w,
    const float* __restrict__ ln_b,
    float* __restrict__ xn)
{
    __shared__ float tile[CC][33];
    __shared__ float part_s[8][32];
    __shared__ float part_q[8][32];
    __shared__ float s_mu[32], s_ri[32];

    const int b  = blockIdx.y;
    const int n0 = blockIdx.x * 32;
    const int tid = threadIdx.x;
    const int n   = tid & 31;
    const int g   = tid >> 5;          // 0..7

    const float* xb = x + (size_t)b * CC * HW;

    // load [192 x 32] tile, coalesced over n
    #pragma unroll
    for (int i = 0; i < 24; i++) {
        int c = g + 8 * i;
        tile[c][n] = xb[(size_t)c * HW + n0 + n];
    }
    __syncthreads();

    // per-column stats: 8 partials per column
    float s = 0.f, q = 0.f;
    #pragma unroll
    for (int j = 0; j < 24; j++) {
        float v = tile[g + 8 * j][n];
        s += v; q += v * v;
    }
    part_s[g][n] = s;
    part_q[g][n] = q;
    __syncthreads();

    if (tid < 32) {
        float ts = 0.f, tq = 0.f;
        #pragma unroll
        for (int j = 0; j < 8; j++) { ts += part_s[j][tid]; tq += part_q[j][tid]; }
        float mu  = ts * (1.0f / CC);
        float var = tq * (1.0f / CC) - mu * mu;
        s_mu[tid] = mu;
        s_ri[tid] = rsqrtf(var + 1e-5f);
    }
    __syncthreads();

    // write xn[b, n, c], coalesced over c
    #pragma unroll
    for (int i = 0; i < 24; i++) {
        int j  = tid + 256 * i;            // 0..6143
        int c  = j % CC;
        int nn = j / CC;
        float v = (tile[c][nn] - s_mu[nn]) * s_ri[nn] * ln_w[c] + ln_b[c];
        xn[((size_t)(b * HW + n0 + nn)) * CC + c] = v;
    }
}

// ------------------------------------------------------------------
// SGEMM: C[m,n] = sum_k A[m,k] * B'[k,n]
//   B_K_MAJOR = true : B stored [n, k] (k contiguous)  -> dot-product GEMM
//   B_K_MAJOR = false: B stored [k, n] (n contiguous)
// Block tile 128(M) x 64(N), K-step 16, 256 threads, 8x4 microtile.
// ------------------------------------------------------------------
template<bool B_K_MAJOR>
__global__ __launch_bounds__(256) void gemm_kernel(
    const float* __restrict__ A, const float* __restrict__ B,
    float* __restrict__ C,
    int K, int lda, int ldb, int ldc,
    size_t strideA, size_t strideB, size_t strideC)
{
    __shared__ float As[16][132];
    __shared__ float Bs[16][68];

    const float* Ab = A + (size_t)blockIdx.z * strideA;
    const float* Bb = B + (size_t)blockIdx.z * strideB;
    float*       Cb = C + (size_t)blockIdx.z * strideC;

    const int tid = threadIdx.x;
    const int tx  = tid & 15;           // 0..15  -> N
    const int ty  = tid >> 4;           // 0..15  -> M
    const int m0  = blockIdx.x * 128;
    const int n0  = blockIdx.y * 64;

    float acc[8][4];
    #pragma unroll
    for (int i = 0; i < 8; i++)
        #pragma unroll
        for (int j = 0; j < 4; j++) acc[i][j] = 0.f;

    const int kk = (tid & 3) * 4;       // 0,4,8,12
    const int rA = tid >> 2;            // 0..63

    for (int k0 = 0; k0 < K; k0 += 16) {
        // A tile -> As[k][m] (transposed store)
        #pragma unroll
        for (int i = 0; i < 2; i++) {
            int m = rA + i * 64;
            float4 v = *(const float4*)&Ab[(size_t)(m0 + m) * lda + k0 + kk];
            As[kk + 0][m] = v.x; As[kk + 1][m] = v.y;
            As[kk + 2][m] = v.z; As[kk + 3][m] = v.w;
        }
        // B tile -> Bs[k][n]
        if (B_K_MAJOR) {
            int nr = rA;                // 0..63
            float4 v = *(const float4*)&Bb[(size_t)(n0 + nr) * ldb + k0 + kk];
            Bs[kk + 0][nr] = v.x; Bs[kk + 1][nr] = v.y;
            Bs[kk + 2][nr] = v.z; Bs[kk + 3][nr] = v.w;
        } else {
            int kr = tid >> 4;          // 0..15
            int nn = (tid & 15) * 4;    // 0..60
            float4 v = *(const float4*)&Bb[(size_t)(k0 + kr) * ldb + n0 + nn];
            *(float4*)&Bs[kr][nn] = v;
        }
        __syncthreads();

        #pragma unroll
        for (int k = 0; k < 16; k++) {
            float4 a0 = *(const float4*)&As[k][ty * 8];
            float4 a1 = *(const float4*)&As[k][ty * 8 + 4];
            float4 b0 = *(const float4*)&Bs[k][tx * 4];
            float a[8] = {a0.x, a0.y, a0.z, a0.w, a1.x, a1.y, a1.z, a1.w};
            float bv[4] = {b0.x, b0.y, b0.z, b0.w};
            #pragma unroll
            for (int i = 0; i < 8; i++)
                #pragma unroll
                for (int j = 0; j < 4; j++)
                    acc[i][j] = fmaf(a[i], bv[j], acc[i][j]);
        }
        __syncthreads();
    }

    #pragma unroll
    for (int i = 0; i < 8; i++) {
        int m = m0 + ty * 8 + i;
        float4 v = make_float4(acc[i][0], acc[i][1], acc[i][2], acc[i][3]);
        *(float4*)&Cb[(size_t)m * ldc + n0 + tx * 4] = v;
    }
}

// ------------------------------------------------------------------
// K4: per-row blend  S <- a1*softmax(S) + a2*relu(S)^2
// one block (256 threads) per row of 2304
// ------------------------------------------------------------------
__global__ __launch_bounds__(256) void blend_kernel(
    float* __restrict__ S,
    const float* __restrict__ w1,
    const float* __restrict__ w2)
{
    __shared__ float red[256];
    float* row = S + (size_t)blockIdx.x * HW;
    const int tid = threadIdx.x;

    float v[9];
    #pragma unroll
    for (int i = 0; i < 9; i++) v[i] = row[tid + 256 * i];

    // row max
    float m = v[0];
    #pragma unroll
    for (int i = 1; i < 9; i++) m = fmaxf(m, v[i]);
    red[tid] = m; __syncthreads();
    for (int s = 128; s > 0; s >>= 1) {
        if (tid < s) red[tid] = fmaxf(red[tid], red[tid + s]);
        __syncthreads();
    }
    const float m_all = red[0];
    __syncthreads();

    // exp + row sum
    float e[9];
    float l = 0.f;
    #pragma unroll
    for (int i = 0; i < 9; i++) { e[i] = expf(v[i] - m_all); l += e[i]; }
    red[tid] = l; __syncthreads();
    for (int s = 128; s > 0; s >>= 1) {
        if (tid < s) red[tid] += red[tid + s];
        __syncthreads();
    }
    const float l_all = red[0];

    const float e1 = expf(w1[0]);
    const float e2 = expf(w2[0]);
    const float inv = 1.0f / (e1 + e2);
    const float a1 = e1 * inv, a2 = e2 * inv;
    const float sc = a1 / l_all;

    #pragma unroll
    for (int i = 0; i < 9; i++) {
        float r = fmaxf(v[i], 0.f);
        row[tid + 256 * i] = e[i] * sc + a2 * r * r;
    }
}

// ------------------------------------------------------------------
// K6: [B,N,C] -> [B,C,H,W] transpose + residual
// ------------------------------------------------------------------
__global__ __launch_bounds__(256) void out_transpose_kernel(
    const float* __restrict__ obnd,
    const float* __restrict__ x,
    float* __restrict__ out)
{
    __shared__ float tile[32][33];
    const int b  = blockIdx.z;
    const int n0 = blockIdx.x * 32;
    const int c0 = blockIdx.y * 32;
    const int tid = threadIdx.x;
    const int a = tid & 31;        // fast index
    const int g = tid >> 5;        // 0..7

    #pragma unroll
    for (int i = 0; i < 4; i++) {
        int nn = g + 8 * i;
        tile[nn][a] = obnd[((size_t)(b * HW + n0 + nn)) * CC + c0 + a];
    }
    __syncthreads();
    #pragma unroll
    for (int i = 0; i < 4; i++) {
        int c = g + 8 * i;
        size_t idx = ((size_t)(b * CC + c0 + c)) * HW + n0 + a;
        out[idx] = tile[a][c] + x[idx];
    }
}

// ------------------------------------------------------------------
// launch
// ------------------------------------------------------------------
extern "C" void kernel_launch(void* const* d_in, const int* in_sizes, int n_in,
                              void* d_out, int out_size)
{
    (void)in_sizes; (void)n_in; (void)out_size;
    const float* x    = (const float*)d_in[0];
    const float* ln_w = (const float*)d_in[1];
    const float* ln_b = (const float*)d_in[2];
    const float* Wq   = (const float*)d_in[3];
    const float* Wk   = (const float*)d_in[4];
    const float* Wv   = (const float*)d_in[5];
    const float* w1   = (const float*)d_in[6];
    const float* w2   = (const float*)d_in[7];
    float* out = (float*)d_out;

    float *xn, *q, *k, *v, *s;
    cudaGetSymbolAddress((void**)&xn, g_xn);
    cudaGetSymbolAddress((void**)&q,  g_q);
    cudaGetSymbolAddress((void**)&k,  g_k);
    cudaGetSymbolAddress((void**)&v,  g_v);
    cudaGetSymbolAddress((void**)&s,  g_s);

    // K1: LN + transpose
    ln_transpose_kernel<<<dim3(HW / 32, BB), 256>>>(x, ln_w, ln_b, xn);

    // K2: Q/K/V projections (M=36864, N=192, K=192), W is [d, c] k-major
    {
        dim3 grid(NTOT / 128, CC / 64, 1);
        gemm_kernel<true><<<grid, 256>>>(xn, Wq, q, CC, CC, CC, CC, 0, 0, 0);
        gemm_kernel<true><<<grid, 256>>>(xn, Wk, k, CC, CC, CC, CC, 0, 0, 0);
        gemm_kernel<true><<<grid, 256>>>(xn, Wv, v, CC, CC, CC, CC, 0, 0, 0);
    }

    // K3: S = Q @ K^T per batch (M=N=2304, K=192)
    {
        dim3 grid(HW / 128, HW / 64, BB);
        gemm_kernel<true><<<grid, 256>>>(q, k, s, CC, CC, CC, HW,
                                         (size_t)HW * CC, (size_t)HW * CC,
                                         (size_t)HW * HW);
    }

    // K4: blend softmax + relu^2
    blend_kernel<<<dim3(NTOT), 256>>>(s, w1, w2);

    // K5: out_bnd = attn @ V per batch (M=2304, N=192, K=2304), V is n-major
    {
        dim3 grid(HW / 128, CC / 64, BB);
        gemm_kernel<false><<<grid, 256>>>(s, v, xn, HW, HW, CC, CC,
                                          (size_t)HW * HW, (size_t)HW * CC,
                                          (size_t)HW * CC);
    }

    // K6: transpose back + residual
    out_transpose_kernel<<<dim3(HW / 32, CC / 32, BB), 256>>>(xn, x, out);
}